// round 2
// baseline (speedup 1.0000x reference)
#include <cuda_runtime.h>

// Problem constants (fixed by the reference generator)
#define MAX_N 100000
#define MAX_E 1000000
#define D_FEAT 64
#define N_ETYPES 8
#define EPS_V 1e-8f

// Scratch (static __device__ globals — no runtime allocation allowed)
__device__ float         g_nw_exp[MAX_N];
__device__ float         g_sum[MAX_N];
__device__ unsigned char g_mask[MAX_N];
__device__ float         g_ft[MAX_N * D_FEAT];
__device__ float         g_ew[N_ETYPES];
__device__ int           g_zero_count;

// ---------------------------------------------------------------------------
// Kernel 0: tiny setup — per-edge-type weight table + reset zero-node counter
// ---------------------------------------------------------------------------
__global__ void k_setup(const float* __restrict__ edge_weight,      // [T,T]
                        const float* __restrict__ edge_weight_param) // [T,1]
{
    int t = threadIdx.x;
    if (t == 0) g_zero_count = 0;
    if (t < N_ETYPES) {
        float acc = 0.f;
        #pragma unroll
        for (int j = 0; j < N_ETYPES; ++j)
            acc += edge_weight[t * N_ETYPES + j] * edge_weight_param[j];
        g_ew[t] = acc + 1.0f;
    }
}

// ---------------------------------------------------------------------------
// Kernel 1: node pass — one warp per node.
// Computes sum|feat|, feat·attn; writes out=feat for non-zero nodes,
// prepares accumulators for zero nodes.
// ---------------------------------------------------------------------------
__global__ void k_node(const float* __restrict__ feat,   // [N,64]
                       const float* __restrict__ attn,   // [1,64]
                       float* __restrict__ out,          // [N,64]
                       int N)
{
    const int warp_in_block = threadIdx.x >> 5;
    const int lane          = threadIdx.x & 31;
    const int n = blockIdx.x * (blockDim.x >> 5) + warp_in_block;
    if (n >= N) return;

    // Each lane owns 2 consecutive floats of the 64-wide row.
    const float2 f = *reinterpret_cast<const float2*>(feat + (size_t)n * D_FEAT + lane * 2);
    const float a0 = __ldg(attn + lane * 2);
    const float a1 = __ldg(attn + lane * 2 + 1);

    float s_abs = fabsf(f.x) + fabsf(f.y);
    float s_dot = f.x * a0 + f.y * a1;

    // Butterfly reduce — full result in every lane.
    #pragma unroll
    for (int off = 16; off > 0; off >>= 1) {
        s_abs += __shfl_xor_sync(0xFFFFFFFFu, s_abs, off);
        s_dot += __shfl_xor_sync(0xFFFFFFFFu, s_dot, off);
    }

    const bool zero_node = (s_abs == 0.0f);

    if (lane == 0) {
        g_mask[n]   = zero_node ? 0 : 1;
        g_nw_exp[n] = zero_node ? 0.0f : expf(s_dot);   // TEMPERATURE == 1
        g_sum[n]    = 0.0f;
        if (zero_node) atomicAdd(&g_zero_count, 1);
    }

    if (!zero_node) {
        // Output is exactly the input row for non-zero nodes.
        *reinterpret_cast<float2*>(out + (size_t)n * D_FEAT + lane * 2) = f;
    } else {
        // Zero the ft accumulator row (only for zero nodes).
        float2 z = make_float2(0.f, 0.f);
        *reinterpret_cast<float2*>(g_ft + (size_t)n * D_FEAT + lane * 2) = z;
    }
}

// ---------------------------------------------------------------------------
// Kernel 2: edge pass — grid-stride; early-exit when no zero nodes exist.
// ---------------------------------------------------------------------------
__global__ void k_edge(const float* __restrict__ feat,
                       const int* __restrict__ src,
                       const int* __restrict__ dst,
                       const int* __restrict__ e_feat,
                       int E)
{
    if (g_zero_count == 0) return;  // broadcast load; all threads exit

    const int stride = gridDim.x * blockDim.x;
    for (int e = blockIdx.x * blockDim.x + threadIdx.x; e < E; e += stride) {
        const int s = src[e];
        const int d = dst[e];
        const float w = g_nw_exp[s];
        atomicAdd(&g_sum[d], w);
        if (g_mask[d] == 0) {
            const float sc = w * g_ew[e_feat[e] - 1];
            const float* fs = feat + (size_t)s * D_FEAT;
            float* fd = g_ft + (size_t)d * D_FEAT;
            #pragma unroll
            for (int k = 0; k < D_FEAT; ++k)
                atomicAdd(fd + k, __ldg(fs + k) * sc);
        }
    }
}

// ---------------------------------------------------------------------------
// Kernel 3: finalize zero-mask nodes — out = ft / denom
// ---------------------------------------------------------------------------
__global__ void k_final(float* __restrict__ out, int N)
{
    if (g_zero_count == 0) return;

    const int warp_in_block = threadIdx.x >> 5;
    const int lane          = threadIdx.x & 31;
    const int n = blockIdx.x * (blockDim.x >> 5) + warp_in_block;
    if (n >= N) return;
    if (g_mask[n] != 0) return;

    const float s = g_sum[n];
    const float inv = 1.0f / ((s < EPS_V) ? 1.0f : s);
    const float2 v = *reinterpret_cast<const float2*>(g_ft + (size_t)n * D_FEAT + lane * 2);
    float2 r = make_float2(v.x * inv, v.y * inv);
    *reinterpret_cast<float2*>(out + (size_t)n * D_FEAT + lane * 2) = r;
}

// ---------------------------------------------------------------------------
extern "C" void kernel_launch(void* const* d_in, const int* in_sizes, int n_in,
                              void* d_out, int out_size)
{
    const float* feat              = (const float*)d_in[0];
    const float* attn              = (const float*)d_in[1];
    const float* edge_weight       = (const float*)d_in[2];
    const float* edge_weight_param = (const float*)d_in[3];
    const int*   src               = (const int*)d_in[4];
    const int*   dst               = (const int*)d_in[5];
    const int*   e_feat            = (const int*)d_in[6];
    float*       out               = (float*)d_out;

    const int N = in_sizes[0] / D_FEAT;   // 100000
    const int E = in_sizes[4];            // 1000000

    k_setup<<<1, 32>>>(edge_weight, edge_weight_param);

    // 8 warps (8 nodes) per 256-thread block
    const int nodes_per_block = 256 / 32;
    const int grid_n = (N + nodes_per_block - 1) / nodes_per_block;
    k_node<<<grid_n, 256>>>(feat, attn, out, N);

    // Grid-stride edge kernel; modest grid so the early-exit path is cheap.
    k_edge<<<1184, 256>>>(feat, src, dst, e_feat, E);

    k_final<<<grid_n, 256>>>(out, N);
}

// round 3
// speedup vs baseline: 1.7586x; 1.7586x over previous
#include <cuda_runtime.h>

// Problem constants (fixed by the reference generator)
#define MAX_N 100000
#define MAX_E 1000000
#define D_FEAT 64
#define N_ETYPES 8
#define EPS_V 1e-8f

// Scratch (static __device__ globals — no runtime allocation allowed)
__device__ float         g_nw_exp[MAX_N];
__device__ float         g_sum[MAX_N];
__device__ unsigned char g_mask[MAX_N];
__device__ float         g_ft[MAX_N * D_FEAT];
__device__ float         g_ew[N_ETYPES];
__device__ int           g_zero_count;

// ---------------------------------------------------------------------------
// Kernel 0: tiny setup — per-edge-type weight table + reset zero-node counter
// ---------------------------------------------------------------------------
__global__ void k_setup(const float* __restrict__ edge_weight,       // [T,T]
                        const float* __restrict__ edge_weight_param) // [T,1]
{
    int t = threadIdx.x;
    if (t == 0) g_zero_count = 0;
    if (t < N_ETYPES) {
        float acc = 0.f;
        #pragma unroll
        for (int j = 0; j < N_ETYPES; ++j)
            acc += edge_weight[t * N_ETYPES + j] * edge_weight_param[j];
        g_ew[t] = acc + 1.0f;
    }
}

// ---------------------------------------------------------------------------
// Kernel 1: node pass — 16 lanes per node (2 nodes per warp), float4 lanes.
// Computes sum|feat|, feat·attn; writes out=feat for non-zero nodes,
// prepares accumulators for zero nodes.
// ---------------------------------------------------------------------------
__global__ void k_node(const float4* __restrict__ feat4,  // [N*16] float4
                       const float4* __restrict__ attn4,  // [16]   float4
                       float4* __restrict__ out4,         // [N*16] float4
                       int N)
{
    const int tid  = blockIdx.x * blockDim.x + threadIdx.x;
    const int n    = tid >> 4;          // node index (16 threads per node)
    const int sub  = threadIdx.x & 15;  // lane within node group
    if (n >= N) return;

    const float4 f = feat4[(size_t)n * 16 + sub];
    const float4 a = __ldg(attn4 + sub);

    float s_abs = fabsf(f.x) + fabsf(f.y) + fabsf(f.z) + fabsf(f.w);
    float s_dot = f.x * a.x + f.y * a.y + f.z * a.z + f.w * a.w;

    // Reduce within the 16-lane group (xor offsets stay inside the group).
    #pragma unroll
    for (int off = 8; off > 0; off >>= 1) {
        s_abs += __shfl_xor_sync(0xFFFFFFFFu, s_abs, off);
        s_dot += __shfl_xor_sync(0xFFFFFFFFu, s_dot, off);
    }

    const bool zero_node = (s_abs == 0.0f);

    if (sub == 0) {
        g_mask[n]   = zero_node ? 0 : 1;
        g_nw_exp[n] = zero_node ? 0.0f : expf(s_dot);   // TEMPERATURE == 1
        g_sum[n]    = 0.0f;
        if (zero_node) atomicAdd(&g_zero_count, 1);
    }

    if (!zero_node) {
        // Output is exactly the input row for non-zero nodes.
        out4[(size_t)n * 16 + sub] = f;
    } else {
        // Zero the ft accumulator row (only for zero nodes).
        reinterpret_cast<float4*>(g_ft)[(size_t)n * 16 + sub] =
            make_float4(0.f, 0.f, 0.f, 0.f);
    }
}

// ---------------------------------------------------------------------------
// Kernel 2: edge pass — grid-stride; early-exit when no zero nodes exist.
// ---------------------------------------------------------------------------
__global__ void k_edge(const float* __restrict__ feat,
                       const int* __restrict__ src,
                       const int* __restrict__ dst,
                       const int* __restrict__ e_feat,
                       int E)
{
    if (g_zero_count == 0) return;  // broadcast load; all threads exit

    const int stride = gridDim.x * blockDim.x;
    for (int e = blockIdx.x * blockDim.x + threadIdx.x; e < E; e += stride) {
        const int s = src[e];
        const int d = dst[e];
        const float w = g_nw_exp[s];
        atomicAdd(&g_sum[d], w);
        if (g_mask[d] == 0) {
            const float sc = w * g_ew[e_feat[e] - 1];
            const float* fs = feat + (size_t)s * D_FEAT;
            float* fd = g_ft + (size_t)d * D_FEAT;
            #pragma unroll
            for (int k = 0; k < D_FEAT; ++k)
                atomicAdd(fd + k, __ldg(fs + k) * sc);
        }
    }
}

// ---------------------------------------------------------------------------
// Kernel 3: finalize zero-mask nodes — out = ft / denom  (grid-stride)
// ---------------------------------------------------------------------------
__global__ void k_final(float4* __restrict__ out4, int N)
{
    if (g_zero_count == 0) return;  // cheap: small grid, one load per thread

    const int stride_nodes = (gridDim.x * blockDim.x) >> 4;
    int n   = (blockIdx.x * blockDim.x + threadIdx.x) >> 4;
    const int sub = threadIdx.x & 15;

    for (; n < N; n += stride_nodes) {
        if (g_mask[n] != 0) continue;
        const float s = g_sum[n];
        const float inv = 1.0f / ((s < EPS_V) ? 1.0f : s);
        const float4 v = reinterpret_cast<const float4*>(g_ft)[(size_t)n * 16 + sub];
        out4[(size_t)n * 16 + sub] = make_float4(v.x * inv, v.y * inv, v.z * inv, v.w * inv);
    }
}

// ---------------------------------------------------------------------------
extern "C" void kernel_launch(void* const* d_in, const int* in_sizes, int n_in,
                              void* d_out, int out_size)
{
    const float* feat              = (const float*)d_in[0];
    const float* attn              = (const float*)d_in[1];
    const float* edge_weight       = (const float*)d_in[2];
    const float* edge_weight_param = (const float*)d_in[3];
    const int*   src               = (const int*)d_in[4];
    const int*   dst               = (const int*)d_in[5];
    const int*   e_feat            = (const int*)d_in[6];
    float*       out               = (float*)d_out;

    const int N = in_sizes[0] / D_FEAT;   // 100000
    const int E = in_sizes[4];            // 1000000

    k_setup<<<1, 32>>>(edge_weight, edge_weight_param);

    // 256 threads = 16 nodes per block
    const int nodes_per_block = 256 / 16;
    const int grid_n = (N + nodes_per_block - 1) / nodes_per_block;  // 6250
    k_node<<<grid_n, 256>>>((const float4*)feat, (const float4*)attn,
                            (float4*)out, N);

    // Grid-stride kernels with small grids: the (common) early-exit path is
    // just 4 waves of one broadcast load each.
    k_edge<<<592, 256>>>(feat, src, dst, e_feat, E);
    k_final<<<592, 256>>>((float4*)out, N);
}